// round 11
// baseline (speedup 1.0000x reference)
#include <cuda_runtime.h>
#include <cuda_fp16.h>

// ---------------------------------------------------------------------------
// DoG 3D: out = blur(x, sigma=1.0, k=9) - blur(x, sigma=1.6, k=15)
// Separable, replicate boundary.
//   pass_wh: W-conv (float4 smem loads, lo in-place fp32, hi -> fp16 smem),
//            H-conv; writes interleaved fp16 (lo01|hi01) u64 per w-pair.
//            47.1KB smem -> 4 blocks/SM.
//   pass_d : D-conv + fused subtract; single 22-deep LDG.64 batch.
// ---------------------------------------------------------------------------

#define NB 2
#define L 160
#define WP2 80                 // w-pairs per row
#define SLAB (L * L)           // 25600
#define VOL (L * L * L)        // 4096000
#define TOT (NB * VOL)         // 8192000

typedef unsigned long long u64;
typedef unsigned int u32;

// Interleaved fp16 intermediates: per w-pair, low 32b = lo01 half2, high = hi01.
__device__ u64 g_wh[TOT / 2];

// Normalized 1D gaussian weights (each sums to 1).
#define KL0 1.338302e-04f
#define KL1 4.431861e-03f
#define KL2 5.399113e-02f
#define KL3 2.419714e-01f
#define KL4 3.989435e-01f

#define KH0 1.739620e-05f
#define KH1 2.203730e-04f
#define KH2 1.888900e-03f
#define KH3 1.095520e-02f
#define KH4 4.299160e-02f
#define KH5 1.141557e-01f
#define KH6 2.051009e-01f
#define KH7 2.493392e-01f

__device__ __forceinline__ float klw(int i) {
    const float v[9] = {KL0, KL1, KL2, KL3, KL4, KL3, KL2, KL1, KL0};
    return v[i];
}
__device__ __forceinline__ float khw(int i) {
    const float v[15] = {KH0, KH1, KH2, KH3, KH4, KH5, KH6, KH7,
                         KH6, KH5, KH4, KH3, KH2, KH1, KH0};
    return v[i];
}

// ---------------- fused pass: conv along W then H ---------------------------
#define HT 32
#define ROWS 46                 // HT + 14 halo rows
#define PADW 176                // input col c = w + 8, c in 0..174
#define SM_IN_F (ROWS * PADW)   // 8096 floats; lo overwrites cols 0..159
#define SM_HI_U (ROWS * WP2)    // 3680 u32 (half2 per w-pair)
#define SMEM_BYTES (SM_IN_F * 4 + SM_HI_U * 4)   // 47104 B -> 4 blocks/SM

__global__ void __launch_bounds__(320, 4) pass_wh_kernel(const float* __restrict__ x) {
    extern __shared__ float sm[];
    float* s_in = sm;               // input (+8 col offset); lo written in place
    u32* s_hi = (u32*)(sm + SM_IN_F);   // W-conv hi as half2 per w-pair

    const int b = blockIdx.x;
    const int slab = b / 5;         // n*160 + d
    const int tile = b % 5;
    const int h0 = tile * HT - 7;
    const int base_g = slab * SLAB;
    const int tid = threadIdx.x;

    // ---- loader: interior float2 pairs + replicated halo columns ----------
    {
        const int wp = tid % WP2;
        const int rg = tid / WP2;   // 0..3
#pragma unroll
        for (int k = 0; k < 12; ++k) {
            const int r = 4 * k + rg;
            if (r < ROWS) {
                int h = h0 + r;
                h = h < 0 ? 0 : (h > (L - 1) ? (L - 1) : h);
                const float2 v = *(const float2*)&x[base_g + h * L + 2 * wp];
                *(float2*)&s_in[r * PADW + 8 + 2 * wp] = v;
            }
        }
        if (tid < 92) {
            const int r = tid >> 1;
            int h = h0 + r;
            h = h < 0 ? 0 : (h > (L - 1) ? (L - 1) : h);
            if ((tid & 1) == 0) {
                const float v = x[base_g + h * L];
                const float2 vv = make_float2(v, v);
                *(float2*)&s_in[r * PADW + 0] = vv;
                *(float2*)&s_in[r * PADW + 2] = vv;
                *(float2*)&s_in[r * PADW + 4] = vv;
                *(float2*)&s_in[r * PADW + 6] = vv;
            } else {
                const float v = x[base_g + h * L + (L - 1)];
                const float2 vv = make_float2(v, v);
                *(float2*)&s_in[r * PADW + 168] = vv;
                *(float2*)&s_in[r * PADW + 170] = vv;
                *(float2*)&s_in[r * PADW + 172] = vv;
                s_in[r * PADW + 174] = v;
            }
        }
    }
    __syncthreads();

    // ---- W-conv: 4 outputs/thread/row, float4 smem loads ------------------
    // lo (fp32) overwrites s_in cols (w-space); hi stored as 2x half2.
    {
        const int w0 = 4 * (tid % 40);
        const int wp0 = w0 / 2;         // first w-pair index (even)
        const int rg8 = tid / 40;       // 0..7
        float v[20];
        {
            const float* row = &s_in[rg8 * PADW + w0];
#pragma unroll
            for (int m = 0; m < 5; ++m) {
                const float4 p = *(const float4*)&row[4 * m];
                v[4 * m] = p.x; v[4 * m + 1] = p.y;
                v[4 * m + 2] = p.z; v[4 * m + 3] = p.w;
            }
        }
        __syncthreads();
#pragma unroll
        for (int k = 0; k < 6; ++k) {
            const int r = 8 * k + rg8;
            if (r < ROWS) {
                float sH[4] = {0.f, 0.f, 0.f, 0.f};
                float sL[4] = {0.f, 0.f, 0.f, 0.f};
#pragma unroll
                for (int t = 0; t < 15; ++t) {
#pragma unroll
                    for (int o = 0; o < 4; ++o)
                        sH[o] = fmaf(v[o + 1 + t], khw(t), sH[o]);
                }
#pragma unroll
                for (int t = 0; t < 9; ++t) {
#pragma unroll
                    for (int o = 0; o < 4; ++o)
                        sL[o] = fmaf(v[o + 4 + t], klw(t), sL[o]);
                }
                *(float4*)&s_in[r * PADW + w0] =
                    make_float4(sL[0], sL[1], sL[2], sL[3]);
                const __half2 h2a = __floats2half2_rn(sH[0], sH[1]);
                const __half2 h2b = __floats2half2_rn(sH[2], sH[3]);
                uint2 hh;
                hh.x = *(const u32*)&h2a;
                hh.y = *(const u32*)&h2b;
                *(uint2*)&s_hi[r * WP2 + wp0] = hh;
            }
            if (k < 5) {
                const int rn = 8 * (k + 1) + rg8;
                if (rn < ROWS) {
                    const float* row = &s_in[rn * PADW + w0];
#pragma unroll
                    for (int m = 0; m < 5; ++m) {
                        const float4 p = *(const float4*)&row[4 * m];
                        v[4 * m] = p.x; v[4 * m + 1] = p.y;
                        v[4 * m + 2] = p.z; v[4 * m + 3] = p.w;
                    }
                }
            }
            __syncthreads();
        }
    }

    // ---- H-conv: w-pair per thread, 8 h-outputs ----------------------------
    // hi accumulated (fp32) from fp16 smem, packed to half2 before lo phase
    // to cap live registers.
    {
        const int wp = tid % WP2;
        const int rg = tid / WP2;   // 0..3
        const int oh0 = rg * 8;
        const int gp0 = (base_g + (tile * HT + oh0) * L) / 2 + wp;

        u32 hiPk[8];
        {
            float2 accH[8];
#pragma unroll
            for (int i = 0; i < 8; ++i) accH[i] = make_float2(0.f, 0.f);
#pragma unroll
            for (int j = 0; j < 22; ++j) {
                const u32 raw = s_hi[(oh0 + j) * WP2 + wp];
                const float2 bp = __half22float2(*(const __half2*)&raw);
#pragma unroll
                for (int i = 0; i < 8; ++i) {
                    const int t = j - i;
                    if (t >= 0 && t < 15) {
                        accH[i].x = fmaf(bp.x, khw(t), accH[i].x);
                        accH[i].y = fmaf(bp.y, khw(t), accH[i].y);
                    }
                }
            }
#pragma unroll
            for (int i = 0; i < 8; ++i) {
                const __half2 hh = __floats2half2_rn(accH[i].x, accH[i].y);
                hiPk[i] = *(const u32*)&hh;
            }
        }
        {
            float2 accL[8];
#pragma unroll
            for (int i = 0; i < 8; ++i) accL[i] = make_float2(0.f, 0.f);
#pragma unroll
            for (int j = 0; j < 16; ++j) {
                const float2 ap = *(const float2*)&s_in[(oh0 + 3 + j) * PADW + 2 * wp];
#pragma unroll
                for (int i = 0; i < 8; ++i) {
                    const int t = j - i;
                    if (t >= 0 && t < 9) {
                        accL[i].x = fmaf(ap.x, klw(t), accL[i].x);
                        accL[i].y = fmaf(ap.y, klw(t), accL[i].y);
                    }
                }
            }
#pragma unroll
            for (int i = 0; i < 8; ++i) {
                const __half2 hl = __floats2half2_rn(accL[i].x, accL[i].y);
                const u32 a = *(const u32*)&hl;
                g_wh[gp0 + i * WP2] = (u64)a | ((u64)hiPk[i] << 32);
            }
        }
    }
}

// ---------------- pass D: conv along D + fused subtract --------------------
// thread -> w-pair, 8 d-outputs; single front-batched 22-load (MLP=22).
__global__ void __launch_bounds__(256, 3) pass_d_kernel(float* __restrict__ out) {
    const int tid = blockIdx.x * 256 + threadIdx.x;   // < 512000
    const int wp = tid % WP2;
    const int rest = tid / WP2;
    const int h = rest % L;
    const int r2 = rest / L;        // 0..39
    const int seg = r2 % 20;
    const int n = r2 / 20;
    const int d0 = seg * 8;
    const int base2 = (n * VOL) / 2 + h * WP2 + wp;   // pair index
    const int ps = SLAB / 2;

    u64 C[22];
#pragma unroll
    for (int j = 0; j < 22; ++j) {
        int d = d0 + j - 7;
        d = d < 0 ? 0 : (d > (L - 1) ? (L - 1) : d);
        C[j] = g_wh[base2 + d * ps];
    }

    float2 acc[8];
#pragma unroll
    for (int i = 0; i < 8; ++i) acc[i] = make_float2(0.f, 0.f);

#pragma unroll
    for (int j = 0; j < 22; ++j) {
        const u32 a = (u32)C[j];
        const u32 bq = (u32)(C[j] >> 32);
        const float2 flo = __half22float2(*(const __half2*)&a);
        const float2 fhi = __half22float2(*(const __half2*)&bq);
#pragma unroll
        for (int i = 0; i < 8; ++i) {
            const int th = j - i;          // high tap
            if (th >= 0 && th < 15) {
                acc[i].x = fmaf(fhi.x, -khw(th), acc[i].x);
                acc[i].y = fmaf(fhi.y, -khw(th), acc[i].y);
            }
            const int tl = j - 3 - i;      // low tap
            if (tl >= 0 && tl < 9) {
                acc[i].x = fmaf(flo.x, klw(tl), acc[i].x);
                acc[i].y = fmaf(flo.y, klw(tl), acc[i].y);
            }
        }
    }
#pragma unroll
    for (int i = 0; i < 8; ++i)
        *(float2*)&out[2 * (base2 + (d0 + i) * ps)] = acc[i];
}

extern "C" void kernel_launch(void* const* d_in, const int* in_sizes, int n_in,
                              void* d_out, int out_size) {
    const float* x = (const float*)d_in[0];
    float* out = (float*)d_out;

    static int attr_done = 0;
    if (!attr_done) {
        cudaFuncSetAttribute(pass_wh_kernel,
                             cudaFuncAttributeMaxDynamicSharedMemorySize, SMEM_BYTES);
        attr_done = 1;
    }

    pass_wh_kernel<<<320 * 5, 320, SMEM_BYTES>>>(x);
    pass_d_kernel<<<2000, 256>>>(out);
}